// round 1
// baseline (speedup 1.0000x reference)
#include <cuda_runtime.h>
#include <math.h>

// Problem constants
#define BB 8
#define NN 2048
#define MM 2048
#define HH 512
#define KD 64

// ---------------- scratch (no allocations allowed) ----------------
__device__ float g_q[BB * KD * NN];   // q transposed: [b][k][n]
__device__ float g_kk[BB * KD * MM];  // k transposed: [b][k][m]
__device__ float g_qn[BB * NN];       // |q|^2 per row
__device__ float g_kn[BB * MM];       // |k|^2 per row
__device__ float g_w[BB * NN];        // atweight = exp(-min_m dist)

// ---------------- f32x2 packed-FMA helpers (Blackwell) ----------------
__device__ __forceinline__ unsigned long long pack2(float lo, float hi) {
    unsigned long long r;
    asm("mov.b64 %0, {%1, %2};" : "=l"(r) : "f"(lo), "f"(hi));
    return r;
}
__device__ __forceinline__ float2 unpack2(unsigned long long v) {
    float2 r;
    asm("mov.b64 {%0, %1}, %2;" : "=f"(r.x), "=f"(r.y) : "l"(v));
    return r;
}
__device__ __forceinline__ void ffma2(unsigned long long& d,
                                      unsigned long long a,
                                      unsigned long long b) {
    asm("fma.rn.f32x2 %0, %1, %2, %0;" : "+l"(d) : "l"(a), "l"(b));
}

// =====================================================================
// Kernel 1: projections q = x @ Wq^T + bq (and k side), stored TRANSPOSED
// [b][c][n], plus row norms. grid = (16384/128, 2), block = 256.
// smem: s_x[32][132] | s_w[32][68] | s_o[64][132]; s_red aliases s_w.
// =====================================================================
#define PROJ_SMEM (16896 + 8704 + 33792)

__global__ __launch_bounds__(256) void proj_kernel(
    const float* __restrict__ X0, const float* __restrict__ Y0,
    const float* __restrict__ Wq, const float* __restrict__ bq,
    const float* __restrict__ Wk, const float* __restrict__ bk)
{
    extern __shared__ char smem[];
    float* s_x = (float*)smem;                    // [32][132]
    float* s_w = (float*)(smem + 16896);          // [32][68]
    float* s_o = (float*)(smem + 16896 + 8704);   // [64][132]
    float* s_red = s_w;                           // [128][17] alias (8704B)

    const int side = blockIdx.y;
    const float* X    = side ? Y0 : X0;
    const float* W    = side ? Wk : Wq;
    const float* bias = side ? bk : bq;
    float* gout  = side ? g_kk : g_q;
    float* gnorm = side ? g_kn : g_qn;

    const int r0 = blockIdx.x * 128;   // global row (b*2048 + n0)
    const int b  = r0 >> 11;
    const int n0 = r0 & 2047;
    const int t  = threadIdx.x;
    const int tx = t & 15, ty = t >> 4;

    unsigned long long acc2[4][4];     // row-pairs (ty*8+2u,+1) x cols (tx*4+j)
#pragma unroll
    for (int u = 0; u < 4; ++u)
#pragma unroll
        for (int j = 0; j < 4; ++j) acc2[u][j] = 0ULL;

    for (int hc = 0; hc < HH; hc += 32) {
        __syncthreads();
        // x tile -> s_x[h][r]
#pragma unroll
        for (int it = 0; it < 16; ++it) {
            int f = t + 256 * it;            // 0..4095
            int h = f & 31, r = f >> 5;
            s_x[h * 132 + r] = X[(size_t)(r0 + r) * HH + hc + h];
        }
        // W tile -> s_w[h][c]
#pragma unroll
        for (int it = 0; it < 8; ++it) {
            int f = t + 256 * it;            // 0..2047
            int h = f & 31, c = f >> 5;
            s_w[h * 68 + c] = W[(size_t)c * HH + hc + h];
        }
        __syncthreads();

#pragma unroll 8
        for (int h = 0; h < 32; ++h) {
            unsigned long long x2[4];
#pragma unroll
            for (int u = 0; u < 4; ++u)
                x2[u] = *(const unsigned long long*)&s_x[h * 132 + ty * 8 + 2 * u];
            float4 wv = *(const float4*)&s_w[h * 68 + tx * 4];
            unsigned long long w2[4];
            w2[0] = pack2(wv.x, wv.x); w2[1] = pack2(wv.y, wv.y);
            w2[2] = pack2(wv.z, wv.z); w2[3] = pack2(wv.w, wv.w);
#pragma unroll
            for (int u = 0; u < 4; ++u)
#pragma unroll
                for (int j = 0; j < 4; ++j) ffma2(acc2[u][j], x2[u], w2[j]);
        }
    }
    __syncthreads();

    // bias add, stage transposed tile, partial norms
    float4 bv = *(const float4*)&bias[tx * 4];
    float bj[4] = {bv.x, bv.y, bv.z, bv.w};
    float pn[8];
#pragma unroll
    for (int i = 0; i < 8; ++i) pn[i] = 0.f;
#pragma unroll
    for (int u = 0; u < 4; ++u)
#pragma unroll
        for (int j = 0; j < 4; ++j) {
            float2 a = unpack2(acc2[u][j]);
            float q0 = a.x + bj[j];
            float q1 = a.y + bj[j];
            int c = tx * 4 + j;
            s_o[c * 132 + ty * 8 + 2 * u]     = q0;
            s_o[c * 132 + ty * 8 + 2 * u + 1] = q1;
            pn[2 * u]     += q0 * q0;
            pn[2 * u + 1] += q1 * q1;
        }
#pragma unroll
    for (int i = 0; i < 8; ++i) s_red[(ty * 8 + i) * 17 + tx] = pn[i];
    __syncthreads();

    // coalesced transposed writeout: gout[b][c][n0+r]
    float* go = gout + (size_t)b * KD * NN + n0;
#pragma unroll
    for (int it = 0; it < 8; ++it) {
        int f4 = t + 256 * it;               // 0..2047 quads over [64][128]
        int c = f4 >> 5;
        int r = (f4 & 31) << 2;
        float4 v = *(const float4*)&s_o[c * 132 + r];
        *(float4*)&go[(size_t)c * NN + r] = v;
    }
    // row-norm reduce across tx
    if (t < 128) {
        float s = 0.f;
#pragma unroll
        for (int j = 0; j < 16; ++j) s += s_red[t * 17 + j];
        gnorm[r0 + t] = s;
    }
}

// =====================================================================
// Kernel 2: fused min-distance "GEMM".
// grid = (N/64, B), block = 256 (tx 0..15 -> m, ty 0..15 -> n).
// Tile: 64 n-rows x 128 m-cols, K=64. k tile pre-scaled by -2 so
// dist = acc + |q|^2 + |k|^2. Running row-min in regs, one smem reduce.
// smem: s_q[64][68] | s_k[64][132] | s_qn[64] | s_kn[128]; s_red aliases s_k.
// =====================================================================
#define DIST_SMEM (17408 + 33792 + 256 + 512)

__global__ __launch_bounds__(256) void dist_kernel()
{
    extern __shared__ char smem[];
    float* s_q  = (float*)smem;                       // [64][68]
    float* s_k  = (float*)(smem + 17408);             // [64][132]
    float* s_qn = (float*)(smem + 17408 + 33792);     // [64]
    float* s_kn = s_qn + 64;                          // [128]
    float* s_red = s_k;                               // [64][17] alias

    const int b  = blockIdx.y;
    const int n0 = blockIdx.x * 64;
    const int t  = threadIdx.x;
    const int tx = t & 15, ty = t >> 4;

    // load q tile (transposed layout) + q norms
    const float* gq = g_q + (size_t)b * KD * NN + n0;
#pragma unroll
    for (int it = 0; it < 16; ++it) {
        int f = t + 256 * it;      // 0..4095 over [64 kk][64 n]
        int kk = f >> 6, n = f & 63;
        s_q[kk * 68 + n] = gq[(size_t)kk * NN + n];
    }
    if (t < 64) s_qn[t] = g_qn[b * NN + n0 + t];
    __syncthreads();

    float qn[4];
#pragma unroll
    for (int i = 0; i < 4; ++i) qn[i] = s_qn[ty * 4 + i];

    float rmin[4];
#pragma unroll
    for (int i = 0; i < 4; ++i) rmin[i] = 1e30f;

    const float* gk = g_kk + (size_t)b * KD * MM;

    for (int m0 = 0; m0 < MM; m0 += 128) {
        __syncthreads();  // previous tile's compute done
        // load k tile scaled by -2 -> s_k[kk][m]
#pragma unroll
        for (int it = 0; it < 8; ++it) {
            int f4 = t + 256 * it;          // 0..2047 quads over [64][128]
            int kk = f4 >> 5;
            int m  = (f4 & 31) << 2;
            float4 v = *(const float4*)&gk[(size_t)kk * MM + m0 + m];
            float4 sv = make_float4(-2.f * v.x, -2.f * v.y, -2.f * v.z, -2.f * v.w);
            *(float4*)&s_k[kk * 132 + m] = sv;
        }
        if (t < 128) s_kn[t] = g_kn[b * MM + m0 + t];
        __syncthreads();

        float kn[8];
#pragma unroll
        for (int j = 0; j < 8; ++j) kn[j] = s_kn[tx * 8 + j];

        unsigned long long acc2[4][4];
#pragma unroll
        for (int i = 0; i < 4; ++i)
#pragma unroll
            for (int j = 0; j < 4; ++j) acc2[i][j] = 0ULL;

#pragma unroll 16
        for (int kk = 0; kk < KD; ++kk) {
            float4 qv = *(const float4*)&s_q[kk * 68 + ty * 4];
            unsigned long long q2[4];
            q2[0] = pack2(qv.x, qv.x); q2[1] = pack2(qv.y, qv.y);
            q2[2] = pack2(qv.z, qv.z); q2[3] = pack2(qv.w, qv.w);
            unsigned long long k2[4];
#pragma unroll
            for (int j = 0; j < 4; ++j)
                k2[j] = *(const unsigned long long*)&s_k[kk * 132 + tx * 8 + 2 * j];
#pragma unroll
            for (int i = 0; i < 4; ++i)
#pragma unroll
                for (int j = 0; j < 4; ++j) ffma2(acc2[i][j], q2[i], k2[j]);
        }

        // epilogue: dist = acc + qn + kn, running min
#pragma unroll
        for (int i = 0; i < 4; ++i)
#pragma unroll
            for (int j = 0; j < 4; ++j) {
                float2 a = unpack2(acc2[i][j]);
                float d0 = a.x + qn[i] + kn[2 * j];
                float d1 = a.y + qn[i] + kn[2 * j + 1];
                rmin[i] = fminf(rmin[i], fminf(d0, d1));
            }
    }

    __syncthreads();  // done with s_k before aliasing s_red
#pragma unroll
    for (int i = 0; i < 4; ++i) s_red[(ty * 4 + i) * 17 + tx] = rmin[i];
    __syncthreads();
    if (t < 64) {
        float mv = s_red[t * 17];
#pragma unroll
        for (int j = 1; j < 16; ++j) mv = fminf(mv, s_red[t * 17 + j]);
        g_w[b * NN + n0 + t] = expf(-mv);
    }
}

// =====================================================================
// Kernel 3: rank-1 outer product out[b][n][m] = w[b][n] * w[b][m].
// grid = (N, B), block = 256, vectorized float4 writes. HBM-bound.
// =====================================================================
__global__ __launch_bounds__(256) void outer_kernel(float* __restrict__ out)
{
    const int b = blockIdx.y;
    const int n = blockIdx.x;
    const float wn = g_w[b * NN + n];
    const float4* wv = (const float4*)&g_w[b * NN];
    float4* o = (float4*)(out + ((size_t)b * NN + n) * MM);
#pragma unroll
    for (int it = 0; it < 2; ++it) {
        int j = threadIdx.x + 256 * it;      // 0..511 quads
        float4 v = wv[j];
        o[j] = make_float4(wn * v.x, wn * v.y, wn * v.z, wn * v.w);
    }
}

// =====================================================================
extern "C" void kernel_launch(void* const* d_in, const int* in_sizes, int n_in,
                              void* d_out, int out_size)
{
    const float* x  = (const float*)d_in[0];
    const float* y  = (const float*)d_in[1];
    const float* Wq = (const float*)d_in[2];
    const float* bq = (const float*)d_in[3];
    const float* Wk = (const float*)d_in[4];
    const float* bk = (const float*)d_in[5];
    float* out = (float*)d_out;

    cudaFuncSetAttribute(proj_kernel, cudaFuncAttributeMaxDynamicSharedMemorySize, PROJ_SMEM);
    cudaFuncSetAttribute(dist_kernel, cudaFuncAttributeMaxDynamicSharedMemorySize, DIST_SMEM);

    proj_kernel<<<dim3((BB * NN) / 128, 2), 256, PROJ_SMEM>>>(x, y, Wq, bq, Wk, bk);
    dist_kernel<<<dim3(NN / 64, BB), 256, DIST_SMEM>>>();
    outer_kernel<<<dim3(NN, BB), 256>>>(out);
}

// round 3
// speedup vs baseline: 2.0114x; 2.0114x over previous
#include <cuda_runtime.h>
#include <cuda_bf16.h>
#include <math.h>

// Problem constants
#define BB 8
#define NN 2048
#define MM 2048
#define HH 512
#define KD 64

// ---------------- scratch (no allocations allowed) ----------------
__device__ float g_qn[BB * NN];       // |q|^2 per row
__device__ float g_kn[BB * MM];       // |k|^2 per row
__device__ float g_w[BB * NN];        // atweight = exp(-min_m dist)
__device__ __nv_bfloat16 g_qh[BB * NN * KD];  // q hi split, row-major [row][64]
__device__ __nv_bfloat16 g_ql[BB * NN * KD];  // q lo split
__device__ __nv_bfloat16 g_kh[BB * MM * KD];  // (-2k) hi split
__device__ __nv_bfloat16 g_kl[BB * MM * KD];  // (-2k) lo split

// ---------------- f32x2 packed-FMA helpers (Blackwell) ----------------
__device__ __forceinline__ unsigned long long pack2(float lo, float hi) {
    unsigned long long r;
    asm("mov.b64 %0, {%1, %2};" : "=l"(r) : "f"(lo), "f"(hi));
    return r;
}
__device__ __forceinline__ float2 unpack2(unsigned long long v) {
    float2 r;
    asm("mov.b64 {%0, %1}, %2;" : "=f"(r.x), "=f"(r.y) : "l"(v));
    return r;
}
__device__ __forceinline__ void ffma2(unsigned long long& d,
                                      unsigned long long a,
                                      unsigned long long b) {
    asm("fma.rn.f32x2 %0, %1, %2, %0;" : "+l"(d) : "l"(a), "l"(b));
}

__device__ __forceinline__ unsigned smem_u32(const void* p) {
    unsigned a;
    asm("{ .reg .u64 t; cvta.to.shared.u64 t, %1; cvt.u32.u64 %0, t; }" : "=r"(a) : "l"(p));
    return a;
}

// ---------------- cp.async / ldmatrix / mma helpers (base sm_103 OK) -----
#define CP16(dst, src) asm volatile("cp.async.cg.shared.global [%0], [%1], 16;" :: "r"(dst), "l"(src) : "memory")
#define CP_COMMIT()    asm volatile("cp.async.commit_group;" ::: "memory")
#define CP_WAIT1()     asm volatile("cp.async.wait_group 1;" ::: "memory")
#define CP_WAIT0()     asm volatile("cp.async.wait_group 0;" ::: "memory")

#define LDSM4(r0, r1, r2, r3, a) \
    asm volatile("ldmatrix.sync.aligned.m8n8.x4.shared.b16 {%0,%1,%2,%3}, [%4];" \
                 : "=r"(r0), "=r"(r1), "=r"(r2), "=r"(r3) : "r"(a))

#define MMA16816(c, a, b) \
    asm volatile("mma.sync.aligned.m16n8k16.row.col.f32.bf16.bf16.f32 " \
                 "{%0,%1,%2,%3}, {%4,%5,%6,%7}, {%8,%9}, {%0,%1,%2,%3};" \
                 : "+f"((c)[0]), "+f"((c)[1]), "+f"((c)[2]), "+f"((c)[3]) \
                 : "r"((a)[0]), "r"((a)[1]), "r"((a)[2]), "r"((a)[3]), \
                   "r"((b)[0]), "r"((b)[1]))

// =====================================================================
// Kernel 1: projections q = x @ Wq^T + bq (and k side). Outputs hi/lo
// bf16 splits (k side pre-scaled by -2) + row norms.
// grid = (16384/128, 2), block = 256, 2 CTAs/SM.
// =====================================================================
#define PROJ_SMEM (16896 + 8704 + 34816)

__global__ __launch_bounds__(256, 2) void proj_kernel(
    const float* __restrict__ X0, const float* __restrict__ Y0,
    const float* __restrict__ Wq, const float* __restrict__ bq,
    const float* __restrict__ Wk, const float* __restrict__ bk)
{
    extern __shared__ char smem[];
    float* s_x = (float*)smem;                    // [32][132]
    float* s_w = (float*)(smem + 16896);          // [32][68]
    float* s_o = (float*)(smem + 16896 + 8704);   // [128][68] row-major
    float* s_red = s_w;                           // [128][17] alias

    const int side = blockIdx.y;
    const float* X    = side ? Y0 : X0;
    const float* W    = side ? Wk : Wq;
    const float* bias = side ? bk : bq;
    float* gnorm = side ? g_kn : g_qn;
    __nv_bfloat16* gh = side ? g_kh : g_qh;
    __nv_bfloat16* gl = side ? g_kl : g_ql;
    const float scale = side ? -2.f : 1.f;

    const int r0 = blockIdx.x * 128;
    const int t  = threadIdx.x;
    const int tx = t & 15, ty = t >> 4;

    unsigned long long acc2[4][4];
#pragma unroll
    for (int u = 0; u < 4; ++u)
#pragma unroll
        for (int j = 0; j < 4; ++j) acc2[u][j] = 0ULL;

    for (int hc = 0; hc < HH; hc += 32) {
        __syncthreads();
#pragma unroll
        for (int it = 0; it < 16; ++it) {
            int f = t + 256 * it;
            int h = f & 31, r = f >> 5;
            s_x[h * 132 + r] = X[(size_t)(r0 + r) * HH + hc + h];
        }
#pragma unroll
        for (int it = 0; it < 8; ++it) {
            int f = t + 256 * it;
            int h = f & 31, c = f >> 5;
            s_w[h * 68 + c] = W[(size_t)c * HH + hc + h];
        }
        __syncthreads();

#pragma unroll 8
        for (int h = 0; h < 32; ++h) {
            unsigned long long x2[4];
#pragma unroll
            for (int u = 0; u < 4; ++u)
                x2[u] = *(const unsigned long long*)&s_x[h * 132 + ty * 8 + 2 * u];
            float4 wv = *(const float4*)&s_w[h * 68 + tx * 4];
            unsigned long long w2[4];
            w2[0] = pack2(wv.x, wv.x); w2[1] = pack2(wv.y, wv.y);
            w2[2] = pack2(wv.z, wv.z); w2[3] = pack2(wv.w, wv.w);
#pragma unroll
            for (int u = 0; u < 4; ++u)
#pragma unroll
                for (int j = 0; j < 4; ++j) ffma2(acc2[u][j], x2[u], w2[j]);
        }
    }
    __syncthreads();

    float4 bv = *(const float4*)&bias[tx * 4];
    float bj[4] = {bv.x, bv.y, bv.z, bv.w};
    float pn[8];
#pragma unroll
    for (int i = 0; i < 8; ++i) pn[i] = 0.f;
#pragma unroll
    for (int u = 0; u < 4; ++u)
#pragma unroll
        for (int j = 0; j < 4; ++j) {
            float2 a = unpack2(acc2[u][j]);
            float q0 = a.x + bj[j];
            float q1 = a.y + bj[j];
            int c = tx * 4 + j;
            int r = ty * 8 + 2 * u;
            s_o[r * 68 + c]       = q0;
            s_o[(r + 1) * 68 + c] = q1;
            pn[2 * u]     += q0 * q0;
            pn[2 * u + 1] += q1 * q1;
        }
#pragma unroll
    for (int i = 0; i < 8; ++i) s_red[(ty * 8 + i) * 17 + tx] = pn[i];
    __syncthreads();

    // hi/lo bf16 split writeout (k side scaled by -2), coalesced
#pragma unroll
    for (int it = 0; it < 8; ++it) {
        int f = t + 256 * it;
        int quad = f & 15, r = f >> 4;
        float4 v = *(const float4*)&s_o[r * 68 + quad * 4];
        v.x *= scale; v.y *= scale; v.z *= scale; v.w *= scale;
        __nv_bfloat16 h0 = __float2bfloat16_rn(v.x);
        __nv_bfloat16 h1 = __float2bfloat16_rn(v.y);
        __nv_bfloat16 h2 = __float2bfloat16_rn(v.z);
        __nv_bfloat16 h3 = __float2bfloat16_rn(v.w);
        __nv_bfloat162 hp0; hp0.x = h0; hp0.y = h1;
        __nv_bfloat162 hp1; hp1.x = h2; hp1.y = h3;
        __nv_bfloat162 lp0 = __floats2bfloat162_rn(v.x - __bfloat162float(h0),
                                                   v.y - __bfloat162float(h1));
        __nv_bfloat162 lp1 = __floats2bfloat162_rn(v.z - __bfloat162float(h2),
                                                   v.w - __bfloat162float(h3));
        size_t base = (size_t)(r0 + r) * KD + quad * 4;
        *(__nv_bfloat162*)&gh[base]     = hp0;
        *(__nv_bfloat162*)&gh[base + 2] = hp1;
        *(__nv_bfloat162*)&gl[base]     = lp0;
        *(__nv_bfloat162*)&gl[base + 2] = lp1;
    }
    if (t < 128) {
        float s = 0.f;
#pragma unroll
        for (int j = 0; j < 16; ++j) s += s_red[t * 17 + j];
        gnorm[r0 + t] = s;
    }
}

// =====================================================================
// Kernel 2: HMMA split-bf16 min-distance kernel.
// dist = q·(-2k) + |q|^2 + |k|^2 via 3 bf16 GEMMs (qh*kh + qh*kl + ql*kh)
// accumulated in fp32 mma.sync; kn folded into accumulator init.
// grid = (16, 8), block = 256 (8 warps: 4 row-groups x 2 col-groups).
// SMEM: qh[16K] ql[16K] | 2 x (kh 16K + kl 16K + kn 512 + pad) | qn | red
// =====================================================================
#define OFF_QL   16384
#define OFF_B    32768
#define BUFSZ    33792
#define OFF_QN   (OFF_B + 2 * BUFSZ)          // 100352
#define OFF_RED  (OFF_QN + 512)               // 100864
#define DIST_SMEM (OFF_RED + 4096)            // 104960
#define NT 16

__global__ __launch_bounds__(256) void dist_kernel()
{
    extern __shared__ char smem[];
    const unsigned sb = smem_u32(smem);

    const int b  = blockIdx.y;
    const int n0 = blockIdx.x * 128;
    const int t  = threadIdx.x;
    const int wid = t >> 5, l = t & 31;
    const int wr = (wid & 3) * 32;    // warp q-row base
    const int wc = (wid >> 2) * 64;   // warp k-col base

    const char* gqh = (const char*)g_qh + ((size_t)b * NN + n0) * KD * 2;
    const char* gql = (const char*)g_ql + ((size_t)b * NN + n0) * KD * 2;
    const char* gkh = (const char*)g_kh + (size_t)b * MM * KD * 2;
    const char* gkl = (const char*)g_kl + (size_t)b * MM * KD * 2;
    const char* gkn = (const char*)g_kn + (size_t)b * MM * 4;
    const char* gqn = (const char*)g_qn + ((size_t)b * NN + n0) * 4;

    // ---- G0: A tiles (qh/ql swizzled) + qn ----
#pragma unroll
    for (int it = 0; it < 8; ++it) {
        int f = t + 256 * it;                // 0..2047
        int split = f >> 10, c = f & 1023;
        int row = c >> 3, ch = c & 7;
        unsigned dst = sb + split * 16384 + row * 128 + ((ch * 16) ^ ((row & 7) << 4));
        CP16(dst, (split ? gql : gqh) + c * 16);
    }
    if (t < 32) CP16(sb + OFF_QN + t * 16, gqn + t * 16);
    // k tile 0 into buf 0 (same group)
#pragma unroll
    for (int it = 0; it < 8; ++it) {
        int f = t + 256 * it;
        int split = f >> 10, c = f & 1023;
        int row = c >> 3, ch = c & 7;
        unsigned dst = sb + OFF_B + split * 16384 + row * 128 + ((ch * 16) ^ ((row & 7) << 4));
        CP16(dst, (split ? gkl : gkh) + c * 16);
    }
    if (t < 32) CP16(sb + OFF_B + 32768 + t * 16, gkn + t * 16);
    CP_COMMIT();

    // per-thread ldmatrix geometry
    const int rowA0 = wr + (l & 7) + ((l & 8) ? 8 : 0);
    const int rowB0 = wc + (l & 7) + ((l & 16) ? 8 : 0);
    const int kbA = (l & 16) ? 16 : 0;
    const int kbB = (l & 8) ? 16 : 0;
    const int p = (l & 7) << 4;
    const unsigned aA0 = sb + rowA0 * 128;            // + split*16384 + f16*2048 + xb
    const unsigned aB0 = rowB0 * 128;                  // + bufbase + split*16384 + t8e*1024 + xb

    float rmin[4];
#pragma unroll
    for (int i = 0; i < 4; ++i) rmin[i] = 1e30f;

    for (int i = 0; i < NT; ++i) {
        __syncthreads();
        if (i + 1 < NT) {
            const char* skh = gkh + (size_t)(i + 1) * 128 * KD * 2;
            const char* skl = gkl + (size_t)(i + 1) * 128 * KD * 2;
            unsigned bufb = sb + OFF_B + ((i + 1) & 1) * BUFSZ;
#pragma unroll
            for (int it = 0; it < 8; ++it) {
                int f = t + 256 * it;
                int split = f >> 10, c = f & 1023;
                int row = c >> 3, ch = c & 7;
                unsigned dst = bufb + split * 16384 + row * 128 + ((ch * 16) ^ ((row & 7) << 4));
                CP16(dst, (split ? skl : skh) + c * 16);
            }
            if (t < 32) CP16(bufb + 32768 + t * 16, gkn + (size_t)(i + 1) * 512 + t * 16);
            CP_COMMIT();
            CP_WAIT1();
        } else {
            CP_WAIT0();
        }
        __syncthreads();

        const unsigned bufb = sb + OFF_B + (i & 1) * BUFSZ;

        // accumulator init = kn[col]  (dist = acc + qn at the end)
        float acc[2][8][4];
#pragma unroll
        for (int t8 = 0; t8 < 8; ++t8) {
            float2 kn2 = *(const float2*)(smem + (i & 1) * BUFSZ + OFF_B + 32768
                                          + (wc + t8 * 8 + 2 * (l & 3)) * 4);
#pragma unroll
            for (int f = 0; f < 2; ++f) {
                acc[f][t8][0] = kn2.x; acc[f][t8][1] = kn2.y;
                acc[f][t8][2] = kn2.x; acc[f][t8][3] = kn2.y;
            }
        }

#pragma unroll
        for (int ks = 0; ks < 4; ++ks) {
            const unsigned xbA = (unsigned)((ks * 32 + kbA) ^ p);
            const unsigned xbB = (unsigned)((ks * 32 + kbB) ^ p);
            unsigned ah[2][4], al[2][4], bh[8][2], bl[8][2];
#pragma unroll
            for (int f = 0; f < 2; ++f) {
                LDSM4(ah[f][0], ah[f][1], ah[f][2], ah[f][3], aA0 + f * 2048 + xbA);
                LDSM4(al[f][0], al[f][1], al[f][2], al[f][3], aA0 + OFF_QL + f * 2048 + xbA);
            }
#pragma unroll
            for (int g = 0; g < 4; ++g) {
                unsigned base = bufb + aB0 + g * 2048 + xbB;
                LDSM4(bh[2 * g][0], bh[2 * g][1], bh[2 * g + 1][0], bh[2 * g + 1][1], base);
                LDSM4(bl[2 * g][0], bl[2 * g][1], bl[2 * g + 1][0], bl[2 * g + 1][1], base + 16384);
            }
#pragma unroll
            for (int f = 0; f < 2; ++f)
#pragma unroll
                for (int t8 = 0; t8 < 8; ++t8) {
                    MMA16816(acc[f][t8], ah[f], bh[t8]);
                    MMA16816(acc[f][t8], ah[f], bl[t8]);
                    MMA16816(acc[f][t8], al[f], bh[t8]);
                }
        }

        // running min
#pragma unroll
        for (int f = 0; f < 2; ++f)
#pragma unroll
            for (int t8 = 0; t8 < 8; ++t8) {
                rmin[f * 2]     = fminf(rmin[f * 2],     fminf(acc[f][t8][0], acc[f][t8][1]));
                rmin[f * 2 + 1] = fminf(rmin[f * 2 + 1], fminf(acc[f][t8][2], acc[f][t8][3]));
            }
    }

    // reduce across the 8 partials per q row
    float* s_red = (float*)(smem + OFF_RED);   // [128][8]
    float* s_qn  = (float*)(smem + OFF_QN);
    __syncthreads();
#pragma unroll
    for (int f = 0; f < 2; ++f)
#pragma unroll
        for (int h = 0; h < 2; ++h) {
            int row = wr + f * 16 + (l >> 2) + h * 8;
            s_red[row * 8 + (wid >> 2) * 4 + (l & 3)] = rmin[f * 2 + h];
        }
    __syncthreads();
    if (t < 128) {
        float mv = s_red[t * 8];
#pragma unroll
        for (int j = 1; j < 8; ++j) mv = fminf(mv, s_red[t * 8 + j]);
        g_w[b * NN + n0 + t] = expf(-(mv + s_qn[t]));
    }
}

// =====================================================================
// Kernel 3: rank-1 outer product out[b][n][m] = w[b][n] * w[b][m].
// =====================================================================
__global__ __launch_bounds__(256) void outer_kernel(float* __restrict__ out)
{
    const int b = blockIdx.y;
    const int n = blockIdx.x;
    const float wn = g_w[b * NN + n];
    const float4* wv = (const float4*)&g_w[b * NN];
    float4* o = (float4*)(out + ((size_t)b * NN + n) * MM);
#pragma unroll
    for (int it = 0; it < 2; ++it) {
        int j = threadIdx.x + 256 * it;
        float4 v = wv[j];
        o[j] = make_float4(wn * v.x, wn * v.y, wn * v.z, wn * v.w);
    }
}

// =====================================================================
extern "C" void kernel_launch(void* const* d_in, const int* in_sizes, int n_in,
                              void* d_out, int out_size)
{
    const float* x  = (const float*)d_in[0];
    const float* y  = (const float*)d_in[1];
    const float* Wq = (const float*)d_in[2];
    const float* bq = (const float*)d_in[3];
    const float* Wk = (const float*)d_in[4];
    const float* bk = (const float*)d_in[5];
    float* out = (float*)d_out;

    cudaFuncSetAttribute(proj_kernel, cudaFuncAttributeMaxDynamicSharedMemorySize, PROJ_SMEM);
    cudaFuncSetAttribute(dist_kernel, cudaFuncAttributeMaxDynamicSharedMemorySize, DIST_SMEM);

    proj_kernel<<<dim3((BB * NN) / 128, 2), 256, PROJ_SMEM>>>(x, y, Wq, bq, Wk, bk);
    dist_kernel<<<dim3(NN / 128, BB), 256, DIST_SMEM>>>();
    outer_kernel<<<dim3(NN, BB), 256>>>(out);
}

// round 4
// speedup vs baseline: 2.8848x; 1.4342x over previous
#include <cuda_runtime.h>
#include <cuda_bf16.h>
#include <math.h>

// Problem constants
#define BB 8
#define NN 2048
#define MM 2048
#define HH 512
#define KD 64

// ---------------- scratch (no allocations allowed) ----------------
__device__ float g_qn[BB * NN];       // |q|^2 per row
__device__ float g_kn[BB * MM];       // |k|^2 per row
__device__ float g_w[BB * NN];        // atweight = exp(-min_m dist)
__device__ __nv_bfloat16 g_qh[BB * NN * KD];  // q hi split, row-major [row][64]
__device__ __nv_bfloat16 g_ql[BB * NN * KD];  // q lo split
__device__ __nv_bfloat16 g_kh[BB * MM * KD];  // (-2k) hi split
__device__ __nv_bfloat16 g_kl[BB * MM * KD];  // (-2k) lo split
__device__ __nv_bfloat16 g_wh[2][KD * HH];    // W hi split [side][n][k]
__device__ __nv_bfloat16 g_wl[2][KD * HH];    // W lo split

__device__ __forceinline__ unsigned smem_u32(const void* p) {
    unsigned a;
    asm("{ .reg .u64 t; cvta.to.shared.u64 t, %1; cvt.u32.u64 %0, t; }" : "=r"(a) : "l"(p));
    return a;
}

// ---------------- cp.async / ldmatrix / mma helpers (base sm_103 OK) -----
#define CP16(dst, src) asm volatile("cp.async.cg.shared.global [%0], [%1], 16;" :: "r"(dst), "l"(src) : "memory")
#define CP_COMMIT()    asm volatile("cp.async.commit_group;" ::: "memory")
#define CP_WAIT1()     asm volatile("cp.async.wait_group 1;" ::: "memory")
#define CP_WAIT0()     asm volatile("cp.async.wait_group 0;" ::: "memory")

#define LDSM4(r0, r1, r2, r3, a) \
    asm volatile("ldmatrix.sync.aligned.m8n8.x4.shared.b16 {%0,%1,%2,%3}, [%4];" \
                 : "=r"(r0), "=r"(r1), "=r"(r2), "=r"(r3) : "r"(a))

#define MMA16816(c, a, b) \
    asm volatile("mma.sync.aligned.m16n8k16.row.col.f32.bf16.bf16.f32 " \
                 "{%0,%1,%2,%3}, {%4,%5,%6,%7}, {%8,%9}, {%0,%1,%2,%3};" \
                 : "+f"((c)[0]), "+f"((c)[1]), "+f"((c)[2]), "+f"((c)[3]) \
                 : "r"((a)[0]), "r"((a)[1]), "r"((a)[2]), "r"((a)[3]), \
                   "r"((b)[0]), "r"((b)[1]))

__device__ __forceinline__ unsigned pack_bf2(float a, float b) {
    __nv_bfloat162 t = __floats2bfloat162_rn(a, b);
    return *reinterpret_cast<unsigned*>(&t);
}
__device__ __forceinline__ unsigned pack_h2(__nv_bfloat16 a, __nv_bfloat16 b) {
    __nv_bfloat162 t = __halves2bfloat162(a, b);
    return *reinterpret_cast<unsigned*>(&t);
}

// =====================================================================
// Kernel 0: split W into hi/lo bf16 (one-time, tiny)
// =====================================================================
__global__ void wsplit_kernel(const float* __restrict__ Wq, const float* __restrict__ Wk)
{
    int i = blockIdx.x * 256 + threadIdx.x;     // 0..65535
    int side = i >> 15, j = i & 32767;
    float v = (side ? Wk : Wq)[j];
    __nv_bfloat16 h = __float2bfloat16_rn(v);
    g_wh[side][j] = h;
    g_wl[side][j] = __float2bfloat16_rn(v - __bfloat162float(h));
}

// =====================================================================
// Kernel 1 (v2): HMMA split-bf16 projection.
// q[128rows,64cols] = x[128,512] @ W^T[512,64] + b via 3 bf16 GEMMs.
// x converted on the fly (regs double-buffered); W hi/lo via cp.async.
// grid = (128, 2), block = 256 (8 warps: 4 M x 2 N), 2 CTAs/SM.
// smem: xh[16K] xl[16K] | W double buf 2x(Wh 8K + Wl 8K) = 64K total.
// epilogue aliases: s_o[128][68] f32 @0, s_red @34816.
// =====================================================================
#define PJ_XL   16384
#define PJ_W    32768
#define PJ_SMEM 65536

__global__ __launch_bounds__(256, 2) void proj_kernel(
    const float* __restrict__ X0, const float* __restrict__ Y0,
    const float* __restrict__ bq, const float* __restrict__ bk)
{
    extern __shared__ char smem[];
    const unsigned sb = smem_u32(smem);

    const int side = blockIdx.y;
    const float* X    = side ? Y0 : X0;
    const float* bias = side ? bk : bq;
    const char* gwh = (const char*)g_wh[side];
    const char* gwl = (const char*)g_wl[side];
    float* gnorm = side ? g_kn : g_qn;
    __nv_bfloat16* gh = side ? g_kh : g_qh;
    __nv_bfloat16* gl = side ? g_kl : g_ql;
    const float scale = side ? -2.f : 1.f;

    const int r0 = blockIdx.x * 128;
    const int t  = threadIdx.x;
    const int wid = t >> 5, l = t & 31;
    const int wr = (wid & 3) * 32;     // warp row base
    const int wc = (wid >> 2) * 32;    // warp col base

    // per-thread x-load geometry: 1024 16B-bf16 chunks = [128 rows][8 ch]
    const int xrow = (t + 0 * 256) >> 3;   // pattern: iter it -> chunk t+256*it

    // ---- prologue: x chunk 0 -> regs; W chunk 0 -> smem buf 0 ----
    float4 xbuf[4][2];
#pragma unroll
    for (int it = 0; it < 4; ++it) {
        int c16 = t + 256 * it;
        int row = c16 >> 3, ch = c16 & 7;
        const float* src = X + (size_t)(r0 + row) * HH + ch * 8;
        xbuf[it][0] = *(const float4*)src;
        xbuf[it][1] = *(const float4*)(src + 4);
    }
#pragma unroll
    for (int it = 0; it < 4; ++it) {
        int f = t + 256 * it;              // 0..1023
        int split = f >> 9, c = f & 511;
        int row = c >> 3, ch = c & 7;
        unsigned dst = sb + PJ_W + split * 8192 + row * 128 + ((ch * 16) ^ ((row & 7) << 4));
        CP16(dst, (split ? gwl : gwh) + row * 1024 + ch * 16);
    }
    CP_COMMIT();

    // ldmatrix geometry
    const int rowA0 = wr + (l & 7) + ((l & 8) ? 8 : 0);
    const int rowB0 = wc + (l & 7) + ((l & 16) ? 8 : 0);
    const int kbA = (l & 16) ? 16 : 0;
    const int kbB = (l & 8) ? 16 : 0;
    const int p = (l & 7) << 4;
    const unsigned aA0 = sb + rowA0 * 128;
    const unsigned aB0 = rowB0 * 128;

    float acc[2][4][4];
#pragma unroll
    for (int f = 0; f < 2; ++f)
#pragma unroll
        for (int t8 = 0; t8 < 4; ++t8)
#pragma unroll
            for (int e = 0; e < 4; ++e) acc[f][t8][e] = 0.f;

    for (int i = 0; i < 8; ++i) {
        __syncthreads();   // prev HMMA done -> xh/xl & wbuf[i&1] safe to fill/read
        // convert + store x chunk i
#pragma unroll
        for (int it = 0; it < 4; ++it) {
            int c16 = t + 256 * it;
            int row = c16 >> 3, ch = c16 & 7;
            unsigned off = row * 128 + ((ch * 16) ^ ((row & 7) << 4));
            float4 a = xbuf[it][0], bq4 = xbuf[it][1];
            __nv_bfloat16 h0 = __float2bfloat16_rn(a.x), h1 = __float2bfloat16_rn(a.y);
            __nv_bfloat16 h2 = __float2bfloat16_rn(a.z), h3 = __float2bfloat16_rn(a.w);
            __nv_bfloat16 h4 = __float2bfloat16_rn(bq4.x), h5 = __float2bfloat16_rn(bq4.y);
            __nv_bfloat16 h6 = __float2bfloat16_rn(bq4.z), h7 = __float2bfloat16_rn(bq4.w);
            uint4 hv = make_uint4(pack_h2(h0, h1), pack_h2(h2, h3),
                                  pack_h2(h4, h5), pack_h2(h6, h7));
            uint4 lv = make_uint4(
                pack_bf2(a.x - __bfloat162float(h0), a.y - __bfloat162float(h1)),
                pack_bf2(a.z - __bfloat162float(h2), a.w - __bfloat162float(h3)),
                pack_bf2(bq4.x - __bfloat162float(h4), bq4.y - __bfloat162float(h5)),
                pack_bf2(bq4.z - __bfloat162float(h6), bq4.w - __bfloat162float(h7)));
            *(uint4*)(smem + off) = hv;
            *(uint4*)(smem + PJ_XL + off) = lv;
        }
        if (i < 7) {
            // x chunk i+1 -> regs (latency hidden under HMMA below)
#pragma unroll
            for (int it = 0; it < 4; ++it) {
                int c16 = t + 256 * it;
                int row = c16 >> 3, ch = c16 & 7;
                const float* src = X + (size_t)(r0 + row) * HH + (i + 1) * 64 + ch * 8;
                xbuf[it][0] = *(const float4*)src;
                xbuf[it][1] = *(const float4*)(src + 4);
            }
            // W chunk i+1 -> wbuf[(i+1)&1]
#pragma unroll
            for (int it = 0; it < 4; ++it) {
                int f = t + 256 * it;
                int split = f >> 9, c = f & 511;
                int row = c >> 3, ch = c & 7;
                unsigned dst = sb + PJ_W + ((i + 1) & 1) * 16384 + split * 8192
                               + row * 128 + ((ch * 16) ^ ((row & 7) << 4));
                CP16(dst, (split ? gwl : gwh) + row * 1024 + (i + 1) * 128 + ch * 16);
            }
            CP_COMMIT();
            CP_WAIT1();
        } else {
            CP_WAIT0();
        }
        __syncthreads();

        const unsigned wb = sb + PJ_W + (i & 1) * 16384;
#pragma unroll
        for (int ks = 0; ks < 4; ++ks) {
            const unsigned xbA = (unsigned)((ks * 32 + kbA) ^ p);
            const unsigned xbB = (unsigned)((ks * 32 + kbB) ^ p);
            unsigned ah[2][4], al[2][4], bh[4][2], bl[4][2];
#pragma unroll
            for (int f = 0; f < 2; ++f) {
                LDSM4(ah[f][0], ah[f][1], ah[f][2], ah[f][3], aA0 + f * 2048 + xbA);
                LDSM4(al[f][0], al[f][1], al[f][2], al[f][3], aA0 + PJ_XL + f * 2048 + xbA);
            }
#pragma unroll
            for (int g = 0; g < 2; ++g) {
                unsigned base = wb + aB0 + g * 2048 + xbB;
                LDSM4(bh[2 * g][0], bh[2 * g][1], bh[2 * g + 1][0], bh[2 * g + 1][1], base);
                LDSM4(bl[2 * g][0], bl[2 * g][1], bl[2 * g + 1][0], bl[2 * g + 1][1], base + 8192);
            }
#pragma unroll
            for (int f = 0; f < 2; ++f)
#pragma unroll
                for (int t8 = 0; t8 < 4; ++t8) {
                    MMA16816(acc[f][t8], ah[f], bh[t8]);
                    MMA16816(acc[f][t8], ah[f], bl[t8]);
                    MMA16816(acc[f][t8], al[f], bh[t8]);
                }
        }
    }

    // ---- epilogue: bias, stage to s_o, split writeout, norms ----
    __syncthreads();
    float* s_o = (float*)smem;                 // [128][68]
    float* s_red = (float*)(smem + 34816);
    (void)s_red;
#pragma unroll
    for (int t8 = 0; t8 < 4; ++t8) {
        int col = wc + t8 * 8 + 2 * (l & 3);
        float2 b2 = *(const float2*)&bias[col];
#pragma unroll
        for (int f = 0; f < 2; ++f) {
            int row0 = wr + f * 16 + (l >> 2);
            s_o[row0 * 68 + col]           = acc[f][t8][0] + b2.x;
            s_o[row0 * 68 + col + 1]       = acc[f][t8][1] + b2.y;
            s_o[(row0 + 8) * 68 + col]     = acc[f][t8][2] + b2.x;
            s_o[(row0 + 8) * 68 + col + 1] = acc[f][t8][3] + b2.y;
        }
    }
    __syncthreads();

    // hi/lo bf16 split writeout (k side scaled by -2), coalesced
#pragma unroll
    for (int it = 0; it < 8; ++it) {
        int f = t + 256 * it;
        int quad = f & 15, r = f >> 4;
        float4 v = *(const float4*)&s_o[r * 68 + quad * 4];
        v.x *= scale; v.y *= scale; v.z *= scale; v.w *= scale;
        __nv_bfloat16 h0 = __float2bfloat16_rn(v.x);
        __nv_bfloat16 h1 = __float2bfloat16_rn(v.y);
        __nv_bfloat16 h2 = __float2bfloat16_rn(v.z);
        __nv_bfloat16 h3 = __float2bfloat16_rn(v.w);
        unsigned hp0 = pack_h2(h0, h1), hp1 = pack_h2(h2, h3);
        unsigned lp0 = pack_bf2(v.x - __bfloat162float(h0), v.y - __bfloat162float(h1));
        unsigned lp1 = pack_bf2(v.z - __bfloat162float(h2), v.w - __bfloat162float(h3));
        size_t base = (size_t)(r0 + r) * KD + quad * 4;
        *(unsigned*)&gh[base]     = hp0;
        *(unsigned*)&gh[base + 2] = hp1;
        *(unsigned*)&gl[base]     = lp0;
        *(unsigned*)&gl[base + 2] = lp1;
    }
    // row norms from unscaled q (s_o)
    if (t < 128) {
        float s = 0.f;
#pragma unroll
        for (int j = 0; j < 64; ++j) {
            float v = s_o[t * 68 + j];
            s += v * v;
        }
        gnorm[r0 + t] = s;
    }
    (void)xrow;
}

// =====================================================================
// Kernel 2: HMMA split-bf16 min-distance kernel (unchanged from R3).
// =====================================================================
#define OFF_QL   16384
#define OFF_B    32768
#define BUFSZ    33792
#define OFF_QN   (OFF_B + 2 * BUFSZ)
#define OFF_RED  (OFF_QN + 512)
#define DIST_SMEM (OFF_RED + 4096)
#define NT 16

__global__ __launch_bounds__(256) void dist_kernel()
{
    extern __shared__ char smem[];
    const unsigned sb = smem_u32(smem);

    const int b  = blockIdx.y;
    const int n0 = blockIdx.x * 128;
    const int t  = threadIdx.x;
    const int wid = t >> 5, l = t & 31;
    const int wr = (wid & 3) * 32;
    const int wc = (wid >> 2) * 64;

    const char* gqh = (const char*)g_qh + ((size_t)b * NN + n0) * KD * 2;
    const char* gql = (const char*)g_ql + ((size_t)b * NN + n0) * KD * 2;
    const char* gkh = (const char*)g_kh + (size_t)b * MM * KD * 2;
    const char* gkl = (const char*)g_kl + (size_t)b * MM * KD * 2;
    const char* gkn = (const char*)g_kn + (size_t)b * MM * 4;
    const char* gqn = (const char*)g_qn + ((size_t)b * NN + n0) * 4;

#pragma unroll
    for (int it = 0; it < 8; ++it) {
        int f = t + 256 * it;
        int split = f >> 10, c = f & 1023;
        int row = c >> 3, ch = c & 7;
        unsigned dst = sb + split * 16384 + row * 128 + ((ch * 16) ^ ((row & 7) << 4));
        CP16(dst, (split ? gql : gqh) + c * 16);
    }
    if (t < 32) CP16(sb + OFF_QN + t * 16, gqn + t * 16);
#pragma unroll
    for (int it = 0; it < 8; ++it) {
        int f = t + 256 * it;
        int split = f >> 10, c = f & 1023;
        int row = c >> 3, ch = c & 7;
        unsigned dst = sb + OFF_B + split * 16384 + row * 128 + ((ch * 16) ^ ((row & 7) << 4));
        CP16(dst, (split ? gkl : gkh) + c * 16);
    }
    if (t < 32) CP16(sb + OFF_B + 32768 + t * 16, gkn + t * 16);
    CP_COMMIT();

    const int rowA0 = wr + (l & 7) + ((l & 8) ? 8 : 0);
    const int rowB0 = wc + (l & 7) + ((l & 16) ? 8 : 0);
    const int kbA = (l & 16) ? 16 : 0;
    const int kbB = (l & 8) ? 16 : 0;
    const int p = (l & 7) << 4;
    const unsigned aA0 = sb + rowA0 * 128;
    const unsigned aB0 = rowB0 * 128;

    float rmin[4];
#pragma unroll
    for (int i = 0; i < 4; ++i) rmin[i] = 1e30f;

    for (int i = 0; i < NT; ++i) {
        __syncthreads();
        if (i + 1 < NT) {
            const char* skh = gkh + (size_t)(i + 1) * 128 * KD * 2;
            const char* skl = gkl + (size_t)(i + 1) * 128 * KD * 2;
            unsigned bufb = sb + OFF_B + ((i + 1) & 1) * BUFSZ;
#pragma unroll
            for (int it = 0; it < 8; ++it) {
                int f = t + 256 * it;
                int split = f >> 10, c = f & 1023;
                int row = c >> 3, ch = c & 7;
                unsigned dst = bufb + split * 16384 + row * 128 + ((ch * 16) ^ ((row & 7) << 4));
                CP16(dst, (split ? skl : skh) + c * 16);
            }
            if (t < 32) CP16(bufb + 32768 + t * 16, gkn + (size_t)(i + 1) * 512 + t * 16);
            CP_COMMIT();
            CP_WAIT1();
        } else {
            CP_WAIT0();
        }
        __syncthreads();

        const unsigned bufb = sb + OFF_B + (i & 1) * BUFSZ;

        float acc[2][8][4];
#pragma unroll
        for (int t8 = 0; t8 < 8; ++t8) {
            float2 kn2 = *(const float2*)(smem + (i & 1) * BUFSZ + OFF_B + 32768
                                          + (wc + t8 * 8 + 2 * (l & 3)) * 4);
#pragma unroll
            for (int f = 0; f < 2; ++f) {
                acc[f][t8][0] = kn2.x; acc[f][t8][1] = kn2.y;
                acc[f][t8][2] = kn2.x; acc[f][t8][3] = kn2.y;
            }
        }

#pragma unroll
        for (int ks = 0; ks < 4; ++ks) {
            const unsigned xbA = (unsigned)((ks * 32 + kbA) ^ p);
            const unsigned xbB = (unsigned)((ks * 32 + kbB) ^ p);
            unsigned ah[2][4], al[2][4], bh[8][2], bl[8][2];
#pragma unroll
            for (int f = 0; f < 2; ++f) {
                LDSM4(ah[f][0], ah[f][1], ah[f][2], ah[f][3], aA0 + f * 2048 + xbA);
                LDSM4(al[f][0], al[f][1], al[f][2], al[f][3], aA0 + OFF_QL + f * 2048 + xbA);
            }
#pragma unroll
            for (int g = 0; g < 4; ++g) {
                unsigned base = bufb + aB0 + g * 2048 + xbB;
                LDSM4(bh[2 * g][0], bh[2 * g][1], bh[2 * g + 1][0], bh[2 * g + 1][1], base);
                LDSM4(bl[2 * g][0], bl[2 * g][1], bl[2 * g + 1][0], bl[2 * g + 1][1], base + 16384);
            }
#pragma unroll
            for (int f = 0; f < 2; ++f)
#pragma unroll
                for (int t8 = 0; t8 < 8; ++t8) {
                    MMA16816(acc[f][t8], ah[f], bh[t8]);
                    MMA16816(acc[f][t8], ah[f], bl[t8]);
                    MMA16816(acc[f][t8], al[f], bh[t8]);
                }
        }

#pragma unroll
        for (int f = 0; f < 2; ++f)
#pragma unroll
            for (int t8 = 0; t8 < 8; ++t8) {
                rmin[f * 2]     = fminf(rmin[f * 2],     fminf(acc[f][t8][0], acc[f][t8][1]));
                rmin[f * 2 + 1] = fminf(rmin[f * 2 + 1], fminf(acc[f][t8][2], acc[f][t8][3]));
            }
    }

    float* s_red = (float*)(smem + OFF_RED);
    float* s_qn  = (float*)(smem + OFF_QN);
    __syncthreads();
#pragma unroll
    for (int f = 0; f < 2; ++f)
#pragma unroll
        for (int h = 0; h < 2; ++h) {
            int row = wr + f * 16 + (l >> 2) + h * 8;
            s_red[row * 8 + (wid >> 2) * 4 + (l & 3)] = rmin[f * 2 + h];
        }
    __syncthreads();
    if (t < 128) {
        float mv = s_red[t * 8];
#pragma unroll
        for (int j = 1; j < 8; ++j) mv = fminf(mv, s_red[t * 8 + j]);
        g_w[b * NN + n0 + t] = expf(-(mv + s_qn[t]));
    }
}

// =====================================================================
// Kernel 3: rank-1 outer product out[b][n][m] = w[b][n] * w[b][m].
// =====================================================================
__global__ __launch_bounds__(256) void outer_kernel(float* __restrict__ out)
{
    const int b = blockIdx.y;
    const int n = blockIdx.x;
    const float wn = g_w[b * NN + n];
    const float4* wv = (const float4*)&g_w[b * NN];
    float4* o = (float4*)(out + ((size_t)b * NN + n) * MM);
#pragma unroll
    for (int it = 0; it < 2; ++it) {
        int j = threadIdx.x + 256 * it;
        float4 v = wv[j];
        o[j] = make_float4(wn * v.x, wn * v.y, wn * v.z, wn * v.w);
    }
}

// =====================================================================
extern "C" void kernel_launch(void* const* d_in, const int* in_sizes, int n_in,
                              void* d_out, int out_size)
{
    const float* x  = (const float*)d_in[0];
    const float* y  = (const float*)d_in[1];
    const float* Wq = (const float*)d_in[2];
    const float* bq = (const float*)d_in[3];
    const float* Wk = (const float*)d_in[4];
    const float* bk = (const float*)d_in[5];
    float* out = (float*)d_out;

    cudaFuncSetAttribute(proj_kernel, cudaFuncAttributeMaxDynamicSharedMemorySize, PJ_SMEM);
    cudaFuncSetAttribute(dist_kernel, cudaFuncAttributeMaxDynamicSharedMemorySize, DIST_SMEM);

    wsplit_kernel<<<256, 256>>>(Wq, Wk);
    proj_kernel<<<dim3(NN * BB / 128, 2), 256, PJ_SMEM>>>(x, y, bq, bk);
    dist_kernel<<<dim3(NN / 128, BB), 256, DIST_SMEM>>>();
    outer_kernel<<<dim3(NN, BB), 256>>>(out);
}